// round 3
// baseline (speedup 1.0000x reference)
#include <cuda_runtime.h>
#include <cstdint>

#define HD 128
#define NMAX 100000
#define EMAX 800000

// ---------------- scratch (device globals; no runtime allocation) ----------------
__device__ __align__(256) float g_L[(size_t)NMAX * HD];   // h @ W
__device__ __align__(256) float g_G[(size_t)NMAX * HD];   // aggregated
__device__ __align__(256) float g_O[(size_t)NMAX * HD];   // layer output
__device__ __align__(256) float g_dinv[NMAX];             // deg, then rsqrt(deg)
__device__ __align__(256) float g_selfw[NMAX];            // dinv*dinv
__device__ __align__(256) int   g_src[EMAX];
__device__ __align__(256) int   g_dst[EMAX];
__device__ __align__(256) float g_ew[EMAX];
__device__ __align__(256) float g_sum[HD];
__device__ __align__(256) float g_sq[HD];
__device__ __align__(256) float g_scale[HD];
__device__ __align__(256) float g_shift[HD];

// ---------------- degree / edge precompute ----------------
__global__ void k_initdeg(int N) {
    int i = blockIdx.x * blockDim.x + threadIdx.x;
    if (i < N) g_dinv[i] = 1.0f;  // self-loop
}

__global__ void k_countdeg(const int* __restrict__ ei, int E) {
    int e = blockIdx.x * blockDim.x + threadIdx.x;
    if (e < E) {
        int d = ei[E + e];
        atomicAdd(&g_dinv[d], 1.0f);
    }
}

__global__ void k_dinv(int N) {
    int i = blockIdx.x * blockDim.x + threadIdx.x;
    if (i < N) {
        float dv = rsqrtf(g_dinv[i]);
        g_dinv[i]  = dv;
        g_selfw[i] = dv * dv;
    }
}

__global__ void k_edges(const int* __restrict__ ei, int E) {
    int e = blockIdx.x * blockDim.x + threadIdx.x;
    if (e < E) {
        int s = ei[e];
        int d = ei[E + e];
        g_src[e] = s;
        g_dst[e] = d;
        g_ew[e]  = g_dinv[s] * g_dinv[d];
    }
}

// ---------------- GEMM: C[N,128] = A[N,128] @ W[128,128] ----------------
__global__ void __launch_bounds__(256) k_gemm(const float* __restrict__ A,
                                              const float* __restrict__ W,
                                              float* __restrict__ C, int N) {
    extern __shared__ float sm[];
    float* As = sm;              // [k][row]  128*128
    float* Ws = sm + 128 * 128;  // [k][col]  128*128

    int tid   = threadIdx.x;
    int rbase = blockIdx.x * 128;

    for (int i = tid; i < 4096; i += 256)
        ((float4*)Ws)[i] = ((const float4*)W)[i];

    for (int i = tid; i < 4096; i += 256) {
        int row = i & 127;
        int kq  = i >> 7;  // 0..31
        int gr  = rbase + row;
        float4 v = make_float4(0.f, 0.f, 0.f, 0.f);
        if (gr < N) v = ((const float4*)(A + (size_t)gr * HD))[kq];
        int k = kq * 4;
        As[(k + 0) * 128 + row] = v.x;
        As[(k + 1) * 128 + row] = v.y;
        As[(k + 2) * 128 + row] = v.z;
        As[(k + 3) * 128 + row] = v.w;
    }
    __syncthreads();

    int tr = tid >> 4, tc = tid & 15;
    int r0 = tr * 8, c0 = tc * 8;
    float acc[8][8];
#pragma unroll
    for (int i = 0; i < 8; i++)
#pragma unroll
        for (int j = 0; j < 8; j++) acc[i][j] = 0.f;

#pragma unroll 4
    for (int k = 0; k < 128; k++) {
        float a[8], b[8];
        *(float4*)(a)     = *(float4*)&As[k * 128 + r0];
        *(float4*)(a + 4) = *(float4*)&As[k * 128 + r0 + 4];
        *(float4*)(b)     = *(float4*)&Ws[k * 128 + c0];
        *(float4*)(b + 4) = *(float4*)&Ws[k * 128 + c0 + 4];
#pragma unroll
        for (int i = 0; i < 8; i++)
#pragma unroll
            for (int j = 0; j < 8; j++) acc[i][j] += a[i] * b[j];
    }

#pragma unroll
    for (int i = 0; i < 8; i++) {
        int row = rbase + r0 + i;
        if (row < N) {
            float4* cp = (float4*)(C + (size_t)row * HD + c0);
            cp[0] = make_float4(acc[i][0], acc[i][1], acc[i][2], acc[i][3]);
            cp[1] = make_float4(acc[i][4], acc[i][5], acc[i][6], acc[i][7]);
        }
    }
}

// ---------------- agg init: G = L * selfw[row] + bias ----------------
__global__ void k_init_agg(const float* __restrict__ L, const float* __restrict__ bias,
                           float* __restrict__ G, int N) {
    int i4 = blockIdx.x * blockDim.x + threadIdx.x;
    if (i4 >= N * 32) return;
    int row = i4 >> 5;
    int c4  = i4 & 31;
    float  w = g_selfw[row];
    float4 v = ((const float4*)L)[i4];
    float4 b = ((const float4*)bias)[c4];
    float4 o;
    o.x = v.x * w + b.x;
    o.y = v.y * w + b.y;
    o.z = v.z * w + b.z;
    o.w = v.w * w + b.w;
    ((float4*)G)[i4] = o;
}

// ---------------- scatter: G[dst] += L[src] * ew  (warp per edge, vector red) ----------------
__global__ void k_scatter(const float* __restrict__ L, float* __restrict__ G, int E) {
    int gtid = blockIdx.x * blockDim.x + threadIdx.x;
    int e    = gtid >> 5;
    int lane = gtid & 31;
    if (e >= E) return;
    int   s = g_src[e];
    int   d = g_dst[e];
    float w = g_ew[e];
    float4 v = ((const float4*)(L + (size_t)s * HD))[lane];
    v.x *= w; v.y *= w; v.z *= w; v.w *= w;
    float* gp = G + (size_t)d * HD + lane * 4;
    asm volatile("red.global.add.v4.f32 [%0], {%1, %2, %3, %4};" ::
                 "l"(gp), "f"(v.x), "f"(v.y), "f"(v.z), "f"(v.w) : "memory");
}

// ---------------- BN ----------------
__global__ void k_zero_stats() {
    int c = threadIdx.x;
    g_sum[c] = 0.f;
    g_sq[c]  = 0.f;
}

#define STAT_ROWS 512
__global__ void k_stats(const float* __restrict__ G, int N) {
    int c  = threadIdx.x;  // 128
    int r0 = blockIdx.x * STAT_ROWS;
    int r1 = min(r0 + STAT_ROWS, N);
    float s = 0.f, q = 0.f;
    for (int r = r0; r < r1; r++) {
        float v = G[(size_t)r * HD + c];
        s += v;
        q += v * v;
    }
    atomicAdd(&g_sum[c], s);
    atomicAdd(&g_sq[c], q);
}

__global__ void k_bn_final(const float* __restrict__ gamma, const float* __restrict__ beta, int N) {
    int c = threadIdx.x;
    float invn = 1.0f / (float)N;
    float mu   = g_sum[c] * invn;
    float var  = g_sq[c] * invn - mu * mu;
    float sc   = gamma[c] * rsqrtf(var + 1e-5f);
    g_scale[c] = sc;
    g_shift[c] = beta[c] - mu * sc;
}

__global__ void k_bn_apply(const float* __restrict__ G, float* __restrict__ O, int N, int relu) {
    int i4 = blockIdx.x * blockDim.x + threadIdx.x;
    if (i4 >= N * 32) return;
    int c4 = i4 & 31;
    float4 v  = ((const float4*)G)[i4];
    float4 sc = ((const float4*)g_scale)[c4];
    float4 sh = ((const float4*)g_shift)[c4];
    float4 o;
    o.x = v.x * sc.x + sh.x;
    o.y = v.y * sc.y + sh.y;
    o.z = v.z * sc.z + sh.z;
    o.w = v.w * sc.w + sh.w;
    if (relu) {
        o.x = fmaxf(o.x, 0.f);
        o.y = fmaxf(o.y, 0.f);
        o.z = fmaxf(o.z, 0.f);
        o.w = fmaxf(o.w, 0.f);
    }
    ((float4*)O)[i4] = o;
}

// ---------------- query dot products (warp per query) ----------------
__global__ void k_query(const float* __restrict__ O, const int* __restrict__ eli,
                        float* __restrict__ out, int Q) {
    int gtid = blockIdx.x * blockDim.x + threadIdx.x;
    int q    = gtid >> 5;
    int lane = gtid & 31;
    if (q >= Q) return;
    int u = eli[q];
    int v = eli[Q + q];
    float4 a = ((const float4*)(O + (size_t)u * HD))[lane];
    float4 b = ((const float4*)(O + (size_t)v * HD))[lane];
    float dot = a.x * b.x + a.y * b.y + a.z * b.z + a.w * b.w;
#pragma unroll
    for (int off = 16; off > 0; off >>= 1)
        dot += __shfl_xor_sync(0xFFFFFFFF, dot, off);
    if (lane == 0) out[q] = dot;
}

// ---------------- host ----------------
extern "C" void kernel_launch(void* const* d_in, const int* in_sizes, int n_in,
                              void* d_out, int out_size) {
    const float* x  = (const float*)d_in[0];
    const float* Wl[3] = {(const float*)d_in[1], (const float*)d_in[5], (const float*)d_in[9]};
    const float* bl[3] = {(const float*)d_in[2], (const float*)d_in[6], (const float*)d_in[10]};
    const float* gl[3] = {(const float*)d_in[3], (const float*)d_in[7], (const float*)d_in[11]};
    const float* bel[3]= {(const float*)d_in[4], (const float*)d_in[8], (const float*)d_in[12]};
    const int* ei  = (const int*)d_in[13];
    const int* eli = (const int*)d_in[14];
    float* out = (float*)d_out;

    int N = in_sizes[0] / HD;
    int E = in_sizes[13] / 2;
    int Q = in_sizes[14] / 2;

    float *pL, *pG, *pO;
    cudaGetSymbolAddress((void**)&pL, g_L);
    cudaGetSymbolAddress((void**)&pG, g_G);
    cudaGetSymbolAddress((void**)&pO, g_O);

    const int GEMM_SMEM = 128 * 128 * 2 * sizeof(float);  // 128 KB
    cudaFuncSetAttribute(k_gemm, cudaFuncAttributeMaxDynamicSharedMemorySize, GEMM_SMEM);

    // --- graph norm precompute ---
    k_initdeg<<<(N + 255) / 256, 256>>>(N);
    k_countdeg<<<(E + 255) / 256, 256>>>(ei, E);
    k_dinv<<<(N + 255) / 256, 256>>>(N);
    k_edges<<<(E + 255) / 256, 256>>>(ei, E);

    int gemm_blocks = (N + 127) / 128;
    int elem_blocks = (N * 32 + 255) / 256;
    int scat_blocks = (E + 7) / 8;
    int stat_blocks = (N + STAT_ROWS - 1) / STAT_ROWS;

    const float* in = x;
    for (int l = 0; l < 3; l++) {
        k_gemm<<<gemm_blocks, 256, GEMM_SMEM>>>(in, Wl[l], pL, N);
        k_init_agg<<<elem_blocks, 256>>>(pL, bl[l], pG, N);
        k_scatter<<<scat_blocks, 256>>>(pL, pG, E);
        k_zero_stats<<<1, 128>>>();
        k_stats<<<stat_blocks, 128>>>(pG, N);
        k_bn_final<<<1, 128>>>(gl[l], bel[l], N);
        k_bn_apply<<<elem_blocks, 256>>>(pG, pO, N, l < 2 ? 1 : 0);
        in = pO;
    }

    k_query<<<(Q + 7) / 8, 256>>>(pO, eli, out, Q);
}

// round 5
// speedup vs baseline: 1.0999x; 1.0999x over previous
#include <cuda_runtime.h>
#include <cstdint>

#define HD 128
#define NMAX 100000
#define EMAX 800000
#define SCAN_T 1024

// ---------------- scratch (device globals) ----------------
__device__ __align__(256) float g_L[(size_t)NMAX * HD];   // h @ W
__device__ __align__(256) float g_G[(size_t)NMAX * HD];   // aggregated (pre-BN)
__device__ __align__(256) float g_dinv[NMAX];
__device__ __align__(256) float g_selfw[NMAX];
__device__ __align__(256) int   g_cnt[NMAX];              // degree (no self loop)
__device__ __align__(256) int   g_rowptr[NMAX + 1];
__device__ __align__(256) int   g_cursor[NMAX];
__device__ __align__(256) int   g_csrc[EMAX];
__device__ __align__(256) float g_cw[EMAX];
__device__ __align__(256) float g_sum[HD];
__device__ __align__(256) float g_sq[HD];
__device__ __align__(256) float g_scale[HD];
__device__ __align__(256) float g_shift[HD];

// ---------------- CSR build ----------------
__global__ void k_zero_cnt(int N) {
    int i = blockIdx.x * blockDim.x + threadIdx.x;
    if (i < N) g_cnt[i] = 0;
}

__global__ void k_hist(const int* __restrict__ ei, int E) {
    int e = blockIdx.x * blockDim.x + threadIdx.x;
    if (e < E) atomicAdd(&g_cnt[ei[E + e]], 1);
}

__global__ void k_dinv(int N) {
    int i = blockIdx.x * blockDim.x + threadIdx.x;
    if (i < N) {
        float dv = rsqrtf((float)g_cnt[i] + 1.0f);
        g_dinv[i]  = dv;
        g_selfw[i] = dv * dv;
    }
}

// single-block exclusive scan over g_cnt -> g_rowptr / g_cursor
__global__ void __launch_bounds__(SCAN_T) k_scan(int N, int E) {
    __shared__ float dummy;  // (unused) keep smem nonzero
    __shared__ int ssum[SCAN_T];
    int tid   = threadIdx.x;
    int chunk = (N + SCAN_T - 1) / SCAN_T;
    int lo = tid * chunk, hi = min(lo + chunk, N);
    int s = 0;
    for (int i = lo; i < hi; i++) s += g_cnt[i];
    ssum[tid] = s;
    __syncthreads();
    // Hillis-Steele inclusive scan
    for (int off = 1; off < SCAN_T; off <<= 1) {
        int v = (tid >= off) ? ssum[tid - off] : 0;
        __syncthreads();
        ssum[tid] += v;
        __syncthreads();
    }
    int base = ssum[tid] - s;  // exclusive prefix of this chunk
    for (int i = lo; i < hi; i++) {
        g_rowptr[i] = base;
        g_cursor[i] = base;
        base += g_cnt[i];
    }
    if (tid == SCAN_T - 1) g_rowptr[N] = E;
    (void)dummy;
}

__global__ void k_fill(const int* __restrict__ ei, int E) {
    int e = blockIdx.x * blockDim.x + threadIdx.x;
    if (e < E) {
        int s = ei[e], d = ei[E + e];
        int pos = atomicAdd(&g_cursor[d], 1);
        g_csrc[pos] = s;
        g_cw[pos]   = g_dinv[s] * g_dinv[d];
    }
}

// ---------------- GEMM: L = act(A) @ W ----------------
// bn=0: act = identity (raw input x); bn=1: act = relu(scale*A + shift)
__global__ void __launch_bounds__(256) k_gemm(const float* __restrict__ A,
                                              const float* __restrict__ W,
                                              float* __restrict__ L, int N, int bn) {
    extern __shared__ float sm[];
    float* As = sm;              // [k][row]  128*128
    float* Ws = sm + 128 * 128;  // [k][col]  128*128

    int tid   = threadIdx.x;
    int rbase = blockIdx.x * 128;

    for (int i = tid; i < 4096; i += 256)
        ((float4*)Ws)[i] = ((const float4*)W)[i];

    for (int i = tid; i < 4096; i += 256) {
        int row = i & 127;
        int kq  = i >> 7;  // column quad 0..31
        int gr  = rbase + row;
        float4 v = make_float4(0.f, 0.f, 0.f, 0.f);
        if (gr < N) v = ((const float4*)(A + (size_t)gr * HD))[kq];
        if (bn) {
            float4 sc = ((const float4*)g_scale)[kq];
            float4 sh = ((const float4*)g_shift)[kq];
            v.x = fmaxf(v.x * sc.x + sh.x, 0.f);
            v.y = fmaxf(v.y * sc.y + sh.y, 0.f);
            v.z = fmaxf(v.z * sc.z + sh.z, 0.f);
            v.w = fmaxf(v.w * sc.w + sh.w, 0.f);
        }
        int k = kq * 4;
        As[(k + 0) * 128 + row] = v.x;
        As[(k + 1) * 128 + row] = v.y;
        As[(k + 2) * 128 + row] = v.z;
        As[(k + 3) * 128 + row] = v.w;
    }
    __syncthreads();

    int tr = tid >> 4, tc = tid & 15;
    int r0 = tr * 8, c0 = tc * 8;
    float acc[8][8];
#pragma unroll
    for (int i = 0; i < 8; i++)
#pragma unroll
        for (int j = 0; j < 8; j++) acc[i][j] = 0.f;

#pragma unroll 4
    for (int k = 0; k < 128; k++) {
        float a[8], b[8];
        *(float4*)(a)     = *(float4*)&As[k * 128 + r0];
        *(float4*)(a + 4) = *(float4*)&As[k * 128 + r0 + 4];
        *(float4*)(b)     = *(float4*)&Ws[k * 128 + c0];
        *(float4*)(b + 4) = *(float4*)&Ws[k * 128 + c0 + 4];
#pragma unroll
        for (int i = 0; i < 8; i++)
#pragma unroll
            for (int j = 0; j < 8; j++) acc[i][j] += a[i] * b[j];
    }

#pragma unroll
    for (int i = 0; i < 8; i++) {
        int row = rbase + r0 + i;
        if (row < N) {
            float4* cp = (float4*)(L + (size_t)row * HD + c0);
            cp[0] = make_float4(acc[i][0], acc[i][1], acc[i][2], acc[i][3]);
            cp[1] = make_float4(acc[i][4], acc[i][5], acc[i][6], acc[i][7]);
        }
    }
}

// ---------------- aggregate: G[row] = selfw*L[row] + bias + sum_e w*L[src] ----------------
// one warp per row; lane owns 4 columns
__global__ void __launch_bounds__(256) k_aggregate(const float* __restrict__ L,
                                                   const float* __restrict__ bias,
                                                   float* __restrict__ G, int N) {
    int wid  = threadIdx.x >> 5;
    int lane = threadIdx.x & 31;
    int row  = blockIdx.x * 8 + wid;
    if (row >= N) return;

    float4 b  = ((const float4*)bias)[lane];
    float  sw = g_selfw[row];
    float4 sv = ((const float4*)(L + (size_t)row * HD))[lane];
    float4 acc;
    acc.x = sv.x * sw + b.x;
    acc.y = sv.y * sw + b.y;
    acc.z = sv.z * sw + b.z;
    acc.w = sv.w * sw + b.w;

    int p0 = g_rowptr[row], p1 = g_rowptr[row + 1];
    for (int p = p0; p < p1; p++) {
        int   s = g_csrc[p];
        float w = g_cw[p];
        float4 v = ((const float4*)(L + (size_t)s * HD))[lane];
        acc.x += v.x * w;
        acc.y += v.y * w;
        acc.z += v.z * w;
        acc.w += v.w * w;
    }
    ((float4*)(G + (size_t)row * HD))[lane] = acc;
}

// ---------------- BN stats ----------------
__global__ void k_zero_stats() {
    int c = threadIdx.x;
    g_sum[c] = 0.f;
    g_sq[c]  = 0.f;
}

#define STAT_ROWS 512
__global__ void k_stats(const float* __restrict__ G, int N) {
    int c  = threadIdx.x;  // 128
    int r0 = blockIdx.x * STAT_ROWS;
    int r1 = min(r0 + STAT_ROWS, N);
    float s = 0.f, q = 0.f;
    for (int r = r0; r < r1; r++) {
        float v = G[(size_t)r * HD + c];
        s += v;
        q += v * v;
    }
    atomicAdd(&g_sum[c], s);
    atomicAdd(&g_sq[c], q);
}

__global__ void k_bn_final(const float* __restrict__ gamma, const float* __restrict__ beta, int N) {
    int c = threadIdx.x;
    float invn = 1.0f / (float)N;
    float mu   = g_sum[c] * invn;
    float var  = g_sq[c] * invn - mu * mu;
    float sc   = gamma[c] * rsqrtf(var + 1e-5f);
    g_scale[c] = sc;
    g_shift[c] = beta[c] - mu * sc;
}

// ---------------- query: dot(BN(G[u]), BN(G[v])), no relu ----------------
__global__ void k_query(const float* __restrict__ G, const int* __restrict__ eli,
                        float* __restrict__ out, int Q) {
    int gtid = blockIdx.x * blockDim.x + threadIdx.x;
    int q    = gtid >> 5;
    int lane = gtid & 31;
    if (q >= Q) return;
    int u = eli[q];
    int v = eli[Q + q];
    float4 sc = ((const float4*)g_scale)[lane];
    float4 sh = ((const float4*)g_shift)[lane];
    float4 a = ((const float4*)(G + (size_t)u * HD))[lane];
    float4 b = ((const float4*)(G + (size_t)v * HD))[lane];
    a.x = a.x * sc.x + sh.x; a.y = a.y * sc.y + sh.y;
    a.z = a.z * sc.z + sh.z; a.w = a.w * sc.w + sh.w;
    b.x = b.x * sc.x + sh.x; b.y = b.y * sc.y + sh.y;
    b.z = b.z * sc.z + sh.z; b.w = b.w * sc.w + sh.w;
    float dot = a.x * b.x + a.y * b.y + a.z * b.z + a.w * b.w;
#pragma unroll
    for (int off = 16; off > 0; off >>= 1)
        dot += __shfl_xor_sync(0xFFFFFFFF, dot, off);
    if (lane == 0) out[q] = dot;
}

// ---------------- host ----------------
extern "C" void kernel_launch(void* const* d_in, const int* in_sizes, int n_in,
                              void* d_out, int out_size) {
    const float* x  = (const float*)d_in[0];
    const float* Wl[3] = {(const float*)d_in[1], (const float*)d_in[5], (const float*)d_in[9]};
    const float* bl[3] = {(const float*)d_in[2], (const float*)d_in[6], (const float*)d_in[10]};
    const float* gl[3] = {(const float*)d_in[3], (const float*)d_in[7], (const float*)d_in[11]};
    const float* bel[3]= {(const float*)d_in[4], (const float*)d_in[8], (const float*)d_in[12]};
    const int* ei  = (const int*)d_in[13];
    const int* eli = (const int*)d_in[14];
    float* out = (float*)d_out;

    int N = in_sizes[0] / HD;
    int E = in_sizes[13] / 2;
    int Q = in_sizes[14] / 2;

    float *pL, *pG;
    cudaGetSymbolAddress((void**)&pL, g_L);
    cudaGetSymbolAddress((void**)&pG, g_G);

    const int GEMM_SMEM = 128 * 128 * 2 * sizeof(float);  // 128 KB
    cudaFuncSetAttribute(k_gemm, cudaFuncAttributeMaxDynamicSharedMemorySize, GEMM_SMEM);

    // --- CSR + norm precompute ---
    k_zero_cnt<<<(N + 255) / 256, 256>>>(N);
    k_hist<<<(E + 255) / 256, 256>>>(ei, E);
    k_dinv<<<(N + 255) / 256, 256>>>(N);
    k_scan<<<1, SCAN_T>>>(N, E);
    k_fill<<<(E + 255) / 256, 256>>>(ei, E);

    int gemm_blocks = (N + 127) / 128;
    int agg_blocks  = (N + 7) / 8;
    int stat_blocks = (N + STAT_ROWS - 1) / STAT_ROWS;

    const float* in = x;
    for (int l = 0; l < 3; l++) {
        k_gemm<<<gemm_blocks, 256, GEMM_SMEM>>>(in, Wl[l], pL, N, l > 0 ? 1 : 0);
        k_aggregate<<<agg_blocks, 256>>>(pL, bl[l], pG, N);
        k_zero_stats<<<1, 128>>>();
        k_stats<<<stat_blocks, 128>>>(pG, N);
        k_bn_final<<<1, 128>>>(gl[l], bel[l], N);
        in = pG;
    }

    k_query<<<(Q + 7) / 8, 256>>>(pG, eli, out, Q);
}

// round 6
// speedup vs baseline: 1.3696x; 1.2453x over previous
#include <cuda_runtime.h>
#include <cstdint>

#define HD 128
#define NMAX 100000
#define EMAX 800000
#define SCAN_CHUNK 1024
#define NBLK ((NMAX + SCAN_CHUNK - 1) / SCAN_CHUNK)   // 98

// ---------------- scratch (device globals) ----------------
__device__ __align__(256) float g_L[(size_t)NMAX * HD];   // h @ W
__device__ __align__(256) float g_G[(size_t)NMAX * HD];   // aggregated (pre-BN)
__device__ __align__(256) float g_dinv[NMAX];
__device__ __align__(256) float g_selfw[NMAX];
__device__ __align__(256) int   g_cnt[NMAX];              // degree (no self loop)
__device__ __align__(256) int   g_rowptr[NMAX + 1];
__device__ __align__(256) int   g_cursor[NMAX];
__device__ __align__(256) int   g_csrc[EMAX];
__device__ __align__(256) float g_cw[EMAX];
__device__ __align__(256) int   g_bsum[NBLK];
__device__ __align__(256) int   g_boff[NBLK];
__device__ __align__(256) float g_sum[HD];
__device__ __align__(256) float g_sq[HD];
__device__ __align__(256) float g_scale[HD];
__device__ __align__(256) float g_shift[HD];

// ---------------- CSR build ----------------
__global__ void k_zero_cnt(int N) {
    int i = blockIdx.x * blockDim.x + threadIdx.x;
    if (i < N) g_cnt[i] = 0;
}

__global__ void k_hist(const int* __restrict__ ei, int E) {
    int e = blockIdx.x * blockDim.x + threadIdx.x;
    if (e < E) atomicAdd(&g_cnt[ei[E + e]], 1);
}

__global__ void k_dinv(int N) {
    int i = blockIdx.x * blockDim.x + threadIdx.x;
    if (i < N) {
        float dv = rsqrtf((float)g_cnt[i] + 1.0f);
        g_dinv[i]  = dv;
        g_selfw[i] = dv * dv;
    }
}

// phase 1: per-block sums of 1024 counts
__global__ void __launch_bounds__(256) k_blocksum(int N) {
    __shared__ int wsum[8];
    int tid  = threadIdx.x;
    int base = blockIdx.x * SCAN_CHUNK + tid * 4;
    int s = 0;
#pragma unroll
    for (int j = 0; j < 4; j++) {
        int i = base + j;
        if (i < N) s += g_cnt[i];
    }
#pragma unroll
    for (int off = 16; off > 0; off >>= 1)
        s += __shfl_down_sync(0xFFFFFFFF, s, off);
    if ((tid & 31) == 0) wsum[tid >> 5] = s;
    __syncthreads();
    if (tid == 0) {
        int t = 0;
#pragma unroll
        for (int w = 0; w < 8; w++) t += wsum[w];
        g_bsum[blockIdx.x] = t;
    }
}

// phase 2: one small block scans NBLK block sums (exclusive) + writes rowptr[N]
__global__ void __launch_bounds__(128) k_scan_bsum(int E, int N) {
    __shared__ int sv[NBLK];
    int tid = threadIdx.x;
    if (tid < NBLK) sv[tid] = g_bsum[tid];
    __syncthreads();
    if (tid == 0) {
        int run = 0;
        for (int i = 0; i < NBLK; i++) {
            g_boff[i] = run;
            run += sv[i];
        }
        g_rowptr[N] = E;
    }
}

// phase 3: each block does exclusive scan of its 1024 counts and emits rowptr/cursor
__global__ void __launch_bounds__(256) k_emit(int N) {
    __shared__ int wexc[8];
    int tid  = threadIdx.x;
    int lane = tid & 31;
    int wid  = tid >> 5;
    int base = blockIdx.x * SCAN_CHUNK + tid * 4;

    int c[4];
#pragma unroll
    for (int j = 0; j < 4; j++) {
        int i = base + j;
        c[j] = (i < N) ? g_cnt[i] : 0;
    }
    int tsum = c[0] + c[1] + c[2] + c[3];

    // warp inclusive scan of tsum
    int inc = tsum;
#pragma unroll
    for (int off = 1; off < 32; off <<= 1) {
        int v = __shfl_up_sync(0xFFFFFFFF, inc, off);
        if (lane >= off) inc += v;
    }
    if (lane == 31) wexc[wid] = inc;
    __syncthreads();
    if (tid == 0) {
        int run = 0;
#pragma unroll
        for (int w = 0; w < 8; w++) {
            int t = wexc[w];
            wexc[w] = run;
            run += t;
        }
    }
    __syncthreads();

    int texc = g_boff[blockIdx.x] + wexc[wid] + (inc - tsum);
    int run = texc;
#pragma unroll
    for (int j = 0; j < 4; j++) {
        int i = base + j;
        if (i < N) {
            g_rowptr[i] = run;
            g_cursor[i] = run;
            run += c[j];
        }
    }
}

__global__ void k_fill(const int* __restrict__ ei, int E) {
    int e = blockIdx.x * blockDim.x + threadIdx.x;
    if (e < E) {
        int s = ei[e], d = ei[E + e];
        int pos = atomicAdd(&g_cursor[d], 1);
        g_csrc[pos] = s;
        g_cw[pos]   = g_dinv[s] * g_dinv[d];
    }
}

// ---------------- GEMM: L = act(A) @ W ----------------
// bn=0: act = identity; bn=1: act = relu(scale*A + shift)
__global__ void __launch_bounds__(256) k_gemm(const float* __restrict__ A,
                                              const float* __restrict__ W,
                                              float* __restrict__ L, int N, int bn) {
    extern __shared__ float sm[];
    float* As = sm;              // [k][row]  128*128
    float* Ws = sm + 128 * 128;  // [k][col]  128*128

    int tid   = threadIdx.x;
    int rbase = blockIdx.x * 128;

    for (int i = tid; i < 4096; i += 256)
        ((float4*)Ws)[i] = ((const float4*)W)[i];

    for (int i = tid; i < 4096; i += 256) {
        int row = i & 127;
        int kq  = i >> 7;
        int gr  = rbase + row;
        float4 v = make_float4(0.f, 0.f, 0.f, 0.f);
        if (gr < N) v = ((const float4*)(A + (size_t)gr * HD))[kq];
        if (bn) {
            float4 sc = ((const float4*)g_scale)[kq];
            float4 sh = ((const float4*)g_shift)[kq];
            v.x = fmaxf(v.x * sc.x + sh.x, 0.f);
            v.y = fmaxf(v.y * sc.y + sh.y, 0.f);
            v.z = fmaxf(v.z * sc.z + sh.z, 0.f);
            v.w = fmaxf(v.w * sc.w + sh.w, 0.f);
        }
        int k = kq * 4;
        As[(k + 0) * 128 + row] = v.x;
        As[(k + 1) * 128 + row] = v.y;
        As[(k + 2) * 128 + row] = v.z;
        As[(k + 3) * 128 + row] = v.w;
    }
    __syncthreads();

    int tr = tid >> 4, tc = tid & 15;
    int r0 = tr * 8, c0 = tc * 8;
    float acc[8][8];
#pragma unroll
    for (int i = 0; i < 8; i++)
#pragma unroll
        for (int j = 0; j < 8; j++) acc[i][j] = 0.f;

#pragma unroll 4
    for (int k = 0; k < 128; k++) {
        float a[8], b[8];
        *(float4*)(a)     = *(float4*)&As[k * 128 + r0];
        *(float4*)(a + 4) = *(float4*)&As[k * 128 + r0 + 4];
        *(float4*)(b)     = *(float4*)&Ws[k * 128 + c0];
        *(float4*)(b + 4) = *(float4*)&Ws[k * 128 + c0 + 4];
#pragma unroll
        for (int i = 0; i < 8; i++)
#pragma unroll
            for (int j = 0; j < 8; j++) acc[i][j] += a[i] * b[j];
    }

#pragma unroll
    for (int i = 0; i < 8; i++) {
        int row = rbase + r0 + i;
        if (row < N) {
            float4* cp = (float4*)(L + (size_t)row * HD + c0);
            cp[0] = make_float4(acc[i][0], acc[i][1], acc[i][2], acc[i][3]);
            cp[1] = make_float4(acc[i][4], acc[i][5], acc[i][6], acc[i][7]);
        }
    }
}

// ---------------- aggregate: G[row] = selfw*L[row] + bias + sum_e w*L[src] ----------------
__global__ void __launch_bounds__(256) k_aggregate(const float* __restrict__ L,
                                                   const float* __restrict__ bias,
                                                   float* __restrict__ G, int N) {
    int wid  = threadIdx.x >> 5;
    int lane = threadIdx.x & 31;
    int row  = blockIdx.x * 8 + wid;
    if (row >= N) return;

    float4 b  = ((const float4*)bias)[lane];
    float  sw = g_selfw[row];
    float4 sv = ((const float4*)(L + (size_t)row * HD))[lane];
    float4 acc;
    acc.x = sv.x * sw + b.x;
    acc.y = sv.y * sw + b.y;
    acc.z = sv.z * sw + b.z;
    acc.w = sv.w * sw + b.w;

    int p0 = g_rowptr[row], p1 = g_rowptr[row + 1];
    for (int p = p0; p < p1; p++) {
        int   s = g_csrc[p];
        float w = g_cw[p];
        float4 v = ((const float4*)(L + (size_t)s * HD))[lane];
        acc.x += v.x * w;
        acc.y += v.y * w;
        acc.z += v.z * w;
        acc.w += v.w * w;
    }
    ((float4*)(G + (size_t)row * HD))[lane] = acc;
}

// ---------------- BN stats ----------------
__global__ void k_zero_stats() {
    int c = threadIdx.x;
    g_sum[c] = 0.f;
    g_sq[c]  = 0.f;
}

#define STAT_ROWS 512
__global__ void k_stats(const float* __restrict__ G, int N) {
    int c  = threadIdx.x;
    int r0 = blockIdx.x * STAT_ROWS;
    int r1 = min(r0 + STAT_ROWS, N);
    float s = 0.f, q = 0.f;
    for (int r = r0; r < r1; r++) {
        float v = G[(size_t)r * HD + c];
        s += v;
        q += v * v;
    }
    atomicAdd(&g_sum[c], s);
    atomicAdd(&g_sq[c], q);
}

__global__ void k_bn_final(const float* __restrict__ gamma, const float* __restrict__ beta, int N) {
    int c = threadIdx.x;
    float invn = 1.0f / (float)N;
    float mu   = g_sum[c] * invn;
    float var  = g_sq[c] * invn - mu * mu;
    float sc   = gamma[c] * rsqrtf(var + 1e-5f);
    g_scale[c] = sc;
    g_shift[c] = beta[c] - mu * sc;
}

// ---------------- query: dot(BN(G[u]), BN(G[v])) ----------------
__global__ void k_query(const float* __restrict__ G, const int* __restrict__ eli,
                        float* __restrict__ out, int Q) {
    int gtid = blockIdx.x * blockDim.x + threadIdx.x;
    int q    = gtid >> 5;
    int lane = gtid & 31;
    if (q >= Q) return;
    int u = eli[q];
    int v = eli[Q + q];
    float4 sc = ((const float4*)g_scale)[lane];
    float4 sh = ((const float4*)g_shift)[lane];
    float4 a = ((const float4*)(G + (size_t)u * HD))[lane];
    float4 b = ((const float4*)(G + (size_t)v * HD))[lane];
    a.x = a.x * sc.x + sh.x; a.y = a.y * sc.y + sh.y;
    a.z = a.z * sc.z + sh.z; a.w = a.w * sc.w + sh.w;
    b.x = b.x * sc.x + sh.x; b.y = b.y * sc.y + sh.y;
    b.z = b.z * sc.z + sh.z; b.w = b.w * sc.w + sh.w;
    float dot = a.x * b.x + a.y * b.y + a.z * b.z + a.w * b.w;
#pragma unroll
    for (int off = 16; off > 0; off >>= 1)
        dot += __shfl_xor_sync(0xFFFFFFFF, dot, off);
    if (lane == 0) out[q] = dot;
}

// ---------------- host ----------------
extern "C" void kernel_launch(void* const* d_in, const int* in_sizes, int n_in,
                              void* d_out, int out_size) {
    const float* x  = (const float*)d_in[0];
    const float* Wl[3] = {(const float*)d_in[1], (const float*)d_in[5], (const float*)d_in[9]};
    const float* bl[3] = {(const float*)d_in[2], (const float*)d_in[6], (const float*)d_in[10]};
    const float* gl[3] = {(const float*)d_in[3], (const float*)d_in[7], (const float*)d_in[11]};
    const float* bel[3]= {(const float*)d_in[4], (const float*)d_in[8], (const float*)d_in[12]};
    const int* ei  = (const int*)d_in[13];
    const int* eli = (const int*)d_in[14];
    float* out = (float*)d_out;

    int N = in_sizes[0] / HD;
    int E = in_sizes[13] / 2;
    int Q = in_sizes[14] / 2;

    float *pL, *pG;
    cudaGetSymbolAddress((void**)&pL, g_L);
    cudaGetSymbolAddress((void**)&pG, g_G);

    const int GEMM_SMEM = 128 * 128 * 2 * sizeof(float);
    cudaFuncSetAttribute(k_gemm, cudaFuncAttributeMaxDynamicSharedMemorySize, GEMM_SMEM);

    // --- CSR + norm precompute ---
    int nblk = (N + SCAN_CHUNK - 1) / SCAN_CHUNK;
    k_zero_cnt<<<(N + 255) / 256, 256>>>(N);
    k_hist<<<(E + 255) / 256, 256>>>(ei, E);
    k_dinv<<<(N + 255) / 256, 256>>>(N);
    k_blocksum<<<nblk, 256>>>(N);
    k_scan_bsum<<<1, 128>>>(E, N);
    k_emit<<<nblk, 256>>>(N);
    k_fill<<<(E + 255) / 256, 256>>>(ei, E);

    int gemm_blocks = (N + 127) / 128;
    int agg_blocks  = (N + 7) / 8;
    int stat_blocks = (N + STAT_ROWS - 1) / STAT_ROWS;

    const float* in = x;
    for (int l = 0; l < 3; l++) {
        k_gemm<<<gemm_blocks, 256, GEMM_SMEM>>>(in, Wl[l], pL, N, l > 0 ? 1 : 0);
        k_aggregate<<<agg_blocks, 256>>>(pL, bl[l], pG, N);
        k_zero_stats<<<1, 128>>>();
        k_stats<<<stat_blocks, 128>>>(pG, N);
        k_bn_final<<<1, 128>>>(gl[l], bel[l], N);
        in = pG;
    }

    k_query<<<(Q + 7) / 8, 256>>>(pG, eli, out, Q);
}